// round 9
// baseline (speedup 1.0000x reference)
#include <cuda_runtime.h>
#include <math.h>

#define HID 64
#define MAXN 100000
#define MAXE 1600000

// Scratch (allocation-free rule: __device__ globals). 16B-aligned for vector access.
__device__ __align__(16) int   g_cnt[MAXN];
__device__ __align__(16) int   g_off[MAXN + 1];
__device__ __align__(16) int   g_bsum[128];
__device__ __align__(16) int   g_esrc[MAXE];
__device__ __align__(16) float g_dinv[MAXN];
__device__ __align__(16) float g_hs[(size_t)MAXN * HID];

// dual-FMA: d = a*b + d on packed f32x2 (sm_100+; ptxas never emits this from C++).
// NOTE: accumulator must be tied through %0 (the "+l" operand) — referencing a
// 4th operand index ICEs nvcc.
#define FMA2(d, a, b) asm("fma.rn.f32x2 %0, %1, %2, %0;" : "+l"(d) : "l"(a), "l"(b))
#define PACK2(out, v) asm("mov.b64 %0, {%1, %1};" : "=l"(out) : "r"(v))

// ---------------------------------------------------------------- init
__global__ void k_init(int N) {
    int i = blockIdx.x * blockDim.x + threadIdx.x;
    if (i < N) g_cnt[i] = 0;
}

// ------------------------------------------------------ degree histogram
__global__ void k_count(const int* __restrict__ dst, int E, int N) {
    int i = blockIdx.x * blockDim.x + threadIdx.x;
    if (i < E) {
        unsigned d = (unsigned)dst[i];
        if (d < (unsigned)N) atomicAdd(&g_cnt[d], 1);
    }
}

// ---------------- scan pass 1: per-block sums (1024 elems/block) + dinv
__global__ void k_scan1(int N) {
    int t = threadIdx.x;
    int i0 = blockIdx.x * 1024 + t * 4;
    int v0 = (i0 + 0 < N) ? g_cnt[i0 + 0] : 0;
    int v1 = (i0 + 1 < N) ? g_cnt[i0 + 1] : 0;
    int v2 = (i0 + 2 < N) ? g_cnt[i0 + 2] : 0;
    int v3 = (i0 + 3 < N) ? g_cnt[i0 + 3] : 0;
    if (i0 + 0 < N) g_dinv[i0 + 0] = rsqrtf((float)(v0 + 1));  // +1 self loop
    if (i0 + 1 < N) g_dinv[i0 + 1] = rsqrtf((float)(v1 + 1));
    if (i0 + 2 < N) g_dinv[i0 + 2] = rsqrtf((float)(v2 + 1));
    if (i0 + 3 < N) g_dinv[i0 + 3] = rsqrtf((float)(v3 + 1));
    int s = v0 + v1 + v2 + v3;
#pragma unroll
    for (int o = 16; o; o >>= 1) s += __shfl_xor_sync(0xFFFFFFFFu, s, o);
    __shared__ int wsum[8];
    if ((t & 31) == 0) wsum[t >> 5] = s;
    __syncthreads();
    if (t == 0) {
        int tot = 0;
#pragma unroll
        for (int w = 0; w < 8; w++) tot += wsum[w];
        g_bsum[blockIdx.x] = tot;
    }
}

// ---------------- scan pass 2: exclusive scan of <=128 block sums (1 block)
__global__ void k_scan2(int nb, int N) {
    __shared__ int sh[128];
    int t = threadIdx.x;
    int v = (t < nb) ? g_bsum[t] : 0;
    sh[t] = v;
    __syncthreads();
#pragma unroll
    for (int o = 1; o < 128; o <<= 1) {
        int a = 0;
        if (t >= o) a = sh[t - o];
        __syncthreads();
        sh[t] += a;
        __syncthreads();
    }
    if (t < nb) g_bsum[t] = sh[t] - v;     // exclusive
    if (t == 127) g_off[N] = sh[127];      // grand total
}

// ---------------- scan pass 3: local re-scan + block offset -> g_off
__global__ void k_scan3(int N) {
    __shared__ int sh[256];
    int t = threadIdx.x;
    int i0 = blockIdx.x * 1024 + t * 4;
    int v0 = (i0 + 0 < N) ? g_cnt[i0 + 0] : 0;
    int v1 = (i0 + 1 < N) ? g_cnt[i0 + 1] : 0;
    int v2 = (i0 + 2 < N) ? g_cnt[i0 + 2] : 0;
    int v3 = (i0 + 3 < N) ? g_cnt[i0 + 3] : 0;
    int s = v0 + v1 + v2 + v3;
    sh[t] = s;
    __syncthreads();
#pragma unroll
    for (int o = 1; o < 256; o <<= 1) {
        int a = 0;
        if (t >= o) a = sh[t - o];
        __syncthreads();
        sh[t] += a;
        __syncthreads();
    }
    int excl = sh[t] - s + g_bsum[blockIdx.x];
    if (i0 + 0 < N) g_off[i0 + 0] = excl;
    if (i0 + 1 < N) g_off[i0 + 1] = excl + v0;
    if (i0 + 2 < N) g_off[i0 + 2] = excl + v0 + v1;
    if (i0 + 3 < N) g_off[i0 + 3] = excl + v0 + v1 + v2;
}

// --------------------------------------------------- CSR edge scatter
// g_cnt doubles as countdown cursor: position = off[d] + (cnt[d] - k)
__global__ void k_scatter(const int* __restrict__ ei, int E, int N) {
    int i = blockIdx.x * blockDim.x + threadIdx.x;
    if (i < E) {
        unsigned s = (unsigned)ei[i];
        unsigned d = (unsigned)ei[E + i];
        if (s < (unsigned)N && d < (unsigned)N) {
            int p = g_off[d] + atomicSub(&g_cnt[d], 1) - 1;
            g_esrc[p] = (int)s;
        }
    }
}

// ------------------------------------------ GEMM: hs = (x @ W) * dinv
// 256 thr, 64 rows/block; thread = (row r=tid>>2, 16 cols at (tid&3)*16).
// Inner product via fma.rn.f32x2: 8 dual-FMAs per k per thread.
__global__ void k_gemm(const float* __restrict__ x, const float* __restrict__ W, int N) {
    __shared__ __align__(16) float Ws[64 * 64];   // W K-chunk [64 x 64]
    __shared__ __align__(16) float xs[64 * 65];   // x tile [64 rows x 64+pad]
    int tid = threadIdx.x;
    int row0 = blockIdx.x * 64;
    int r  = tid >> 2;
    int cq = (tid & 3) * 16;

    const float4* W4 = (const float4*)W;
    const float4* x4 = (const float4*)x;
    float4* Ws4 = (float4*)Ws;

    unsigned long long a0 = 0, a1 = 0, a2 = 0, a3 = 0, a4 = 0, a5 = 0, a6 = 0, a7 = 0;

    for (int kc = 0; kc < 4; kc++) {
#pragma unroll
        for (int i = tid; i < 1024; i += 256) Ws4[i] = W4[kc * 1024 + i];
#pragma unroll
        for (int i = tid; i < 1024; i += 256) {
            int rr = i >> 4, cc = i & 15;
            float4 v = (row0 + rr < N) ? x4[(size_t)(row0 + rr) * 64 + kc * 16 + cc]
                                       : make_float4(0.f, 0.f, 0.f, 0.f);
            float* d = &xs[rr * 65 + cc * 4];
            d[0] = v.x; d[1] = v.y; d[2] = v.z; d[3] = v.w;
        }
        __syncthreads();

#pragma unroll 4
        for (int k = 0; k < 64; k++) {
            float xv = xs[r * 65 + k];
            unsigned long long xx;
            PACK2(xx, __float_as_uint(xv));
            const ulonglong2* wp = (const ulonglong2*)&Ws[k * 64 + cq];
            ulonglong2 wA = wp[0];
            ulonglong2 wB = wp[1];
            ulonglong2 wC = wp[2];
            ulonglong2 wD = wp[3];
            FMA2(a0, xx, wA.x); FMA2(a1, xx, wA.y);
            FMA2(a2, xx, wB.x); FMA2(a3, xx, wB.y);
            FMA2(a4, xx, wC.x); FMA2(a5, xx, wC.y);
            FMA2(a6, xx, wD.x); FMA2(a7, xx, wD.y);
        }
        __syncthreads();
    }

    int row = row0 + r;
    if (row < N) {
        float di = g_dinv[row];
        float2 f0 = *(float2*)&a0, f1 = *(float2*)&a1, f2 = *(float2*)&a2, f3 = *(float2*)&a3;
        float2 f4 = *(float2*)&a4, f5 = *(float2*)&a5, f6 = *(float2*)&a6, f7 = *(float2*)&a7;
        float4* hp = (float4*)&g_hs[(size_t)row * HID + cq];
        hp[0] = make_float4(f0.x * di, f0.y * di, f1.x * di, f1.y * di);
        hp[1] = make_float4(f2.x * di, f2.y * di, f3.x * di, f3.y * di);
        hp[2] = make_float4(f4.x * di, f4.y * di, f5.x * di, f5.y * di);
        hp[3] = make_float4(f6.x * di, f6.y * di, f7.x * di, f7.y * di);
    }
}

// -------------------------- SpMM gather + bias + dot(w2) + sigmoid
// one warp per node; half-warps own alternate edges; lane reads float4 (4 cols).
__global__ void k_spmm(const float* __restrict__ b, const float* __restrict__ w2,
                       const float* __restrict__ b2, float* __restrict__ out, int N) {
    int gwarp = (blockIdx.x * blockDim.x + threadIdx.x) >> 5;
    int lane  = threadIdx.x & 31;
    if (gwarp >= N) return;
    int n = gwarp;
    int half = lane >> 4;          // 0 or 1
    int cg   = lane & 15;          // float4 index within row (16 x 16B = 256B)

    int s = g_off[n];
    int e = g_off[n + 1];
    int cnt = e - s;
    const float4* hs4 = (const float4*)g_hs;

    float4 accA = make_float4(0.f, 0.f, 0.f, 0.f);
    float4 accB = make_float4(0.f, 0.f, 0.f, 0.f);
    int i = half;
    // 2 edges per pass per half -> 4 rows in flight per warp
    for (; i + 2 < cnt; i += 4) {
        int s0 = g_esrc[s + i];
        int s1 = g_esrc[s + i + 2];
        float4 v0 = hs4[(size_t)s0 * 16 + cg];
        float4 v1 = hs4[(size_t)s1 * 16 + cg];
        accA.x += v0.x; accA.y += v0.y; accA.z += v0.z; accA.w += v0.w;
        accB.x += v1.x; accB.y += v1.y; accB.z += v1.z; accB.w += v1.w;
    }
    if (i < cnt) {
        int s0 = g_esrc[s + i];
        float4 v0 = hs4[(size_t)s0 * 16 + cg];
        accA.x += v0.x; accA.y += v0.y; accA.z += v0.z; accA.w += v0.w;
    }
    accA.x += accB.x; accA.y += accB.y; accA.z += accB.z; accA.w += accB.w;
    // combine the two halves (lane l and l^16 hold the same 4 columns)
    accA.x += __shfl_xor_sync(0xFFFFFFFFu, accA.x, 16);
    accA.y += __shfl_xor_sync(0xFFFFFFFFu, accA.y, 16);
    accA.z += __shfl_xor_sync(0xFFFFFFFFu, accA.z, 16);
    accA.w += __shfl_xor_sync(0xFFFFFFFFu, accA.w, 16);

    float4 self = hs4[(size_t)n * 16 + cg];
    float di = g_dinv[n];
    float4 bb = ((const float4*)b)[cg];
    float4 ww = ((const float4*)w2)[cg];
    float p = (di * (accA.x + self.x) + bb.x) * ww.x
            + (di * (accA.y + self.y) + bb.y) * ww.y
            + (di * (accA.z + self.z) + bb.z) * ww.z
            + (di * (accA.w + self.w) + bb.w) * ww.w;
#pragma unroll
    for (int o = 8; o; o >>= 1) p += __shfl_xor_sync(0xFFFFFFFFu, p, o);
    if (lane == 0) {
        float z = p + b2[0];
        out[n] = 1.f / (1.f + expf(-z));
    }
}

// ---------------------------------------------------------------- launch
extern "C" void kernel_launch(void* const* d_in, const int* in_sizes, int n_in,
                              void* d_out, int out_size) {
    const float* x  = (const float*)d_in[0];
    const int*   ei = (const int*)d_in[1];    // int32 (JAX x64 disabled)
    const float* W  = (const float*)d_in[2];
    const float* b  = (const float*)d_in[3];
    const float* w2 = (const float*)d_in[4];
    const float* b2 = (const float*)d_in[5];
    float* out = (float*)d_out;

    int N = out_size;            // 100000 nodes
    int E = in_sizes[1] / 2;     // 1600000 edges
    int nb = (N + 1023) / 1024;  // scan blocks (<=128)

    k_init<<<(N + 255) / 256, 256>>>(N);
    k_count<<<(E + 255) / 256, 256>>>(ei + E, E, N);
    k_scan1<<<nb, 256>>>(N);
    k_gemm<<<(N + 63) / 64, 256>>>(x, W, N);   // slot 4 -> ncu profiles this
    k_scan2<<<1, 128>>>(nb, N);
    k_scan3<<<nb, 256>>>(N);
    k_scatter<<<(E + 255) / 256, 256>>>(ei, E, N);
    k_spmm<<<(N + 7) / 8, 256>>>(b, w2, b2, out, N);
}

// round 10
// speedup vs baseline: 2.7090x; 2.7090x over previous
#include <cuda_runtime.h>
#include <math.h>

#define HID 64
#define MAXN 100000
#define MAXE 1600000

// Scratch (allocation-free rule: __device__ globals). 16B-aligned for vector access.
__device__ __align__(16) int   g_cnt[MAXN];
__device__ __align__(16) int   g_off[MAXN + 1];
__device__ __align__(16) int   g_bsum[128];
__device__ __align__(16) int   g_esrc[MAXE];
__device__ __align__(16) float g_dinv[MAXN];
__device__ __align__(16) float g_hs[(size_t)MAXN * HID];

// dual-FMA: d = a*b + d on packed f32x2 (sm_100+). Accumulator tied through %0.
#define FMA2(d, a, b) asm("fma.rn.f32x2 %0, %1, %2, %0;" : "+l"(d) : "l"(a), "l"(b))
#define PACK2(out, v) asm("mov.b64 %0, {%1, %1};" : "=l"(out) : "r"(v))

// ---------------------------------------------------------------- init
__global__ void k_init(int N) {
    int i = blockIdx.x * blockDim.x + threadIdx.x;
    if (i < N) g_cnt[i] = 0;
}

// ------------------------------------------------------ degree histogram
__global__ void k_count(const int* __restrict__ dst, int E, int N) {
    int i = blockIdx.x * blockDim.x + threadIdx.x;
    if (i < E) {
        unsigned d = (unsigned)dst[i];
        if (d < (unsigned)N) atomicAdd(&g_cnt[d], 1);
    }
}

// ---------------- scan pass 1: per-block sums (1024 elems/block) + dinv
__global__ void k_scan1(int N) {
    int t = threadIdx.x;
    int i0 = blockIdx.x * 1024 + t * 4;
    int v0 = (i0 + 0 < N) ? g_cnt[i0 + 0] : 0;
    int v1 = (i0 + 1 < N) ? g_cnt[i0 + 1] : 0;
    int v2 = (i0 + 2 < N) ? g_cnt[i0 + 2] : 0;
    int v3 = (i0 + 3 < N) ? g_cnt[i0 + 3] : 0;
    if (i0 + 0 < N) g_dinv[i0 + 0] = rsqrtf((float)(v0 + 1));  // +1 self loop
    if (i0 + 1 < N) g_dinv[i0 + 1] = rsqrtf((float)(v1 + 1));
    if (i0 + 2 < N) g_dinv[i0 + 2] = rsqrtf((float)(v2 + 1));
    if (i0 + 3 < N) g_dinv[i0 + 3] = rsqrtf((float)(v3 + 1));
    int s = v0 + v1 + v2 + v3;
#pragma unroll
    for (int o = 16; o; o >>= 1) s += __shfl_xor_sync(0xFFFFFFFFu, s, o);
    __shared__ int wsum[8];
    if ((t & 31) == 0) wsum[t >> 5] = s;
    __syncthreads();
    if (t == 0) {
        int tot = 0;
#pragma unroll
        for (int w = 0; w < 8; w++) tot += wsum[w];
        g_bsum[blockIdx.x] = tot;
    }
}

// ---------------- scan pass 2: exclusive scan of <=128 block sums (1 block)
__global__ void k_scan2(int nb, int N) {
    __shared__ int sh[128];
    int t = threadIdx.x;
    int v = (t < nb) ? g_bsum[t] : 0;
    sh[t] = v;
    __syncthreads();
#pragma unroll
    for (int o = 1; o < 128; o <<= 1) {
        int a = 0;
        if (t >= o) a = sh[t - o];
        __syncthreads();
        sh[t] += a;
        __syncthreads();
    }
    if (t < nb) g_bsum[t] = sh[t] - v;     // exclusive
    if (t == 127) g_off[N] = sh[127];      // grand total
}

// ---------------- scan pass 3: local re-scan + block offset -> g_off
__global__ void k_scan3(int N) {
    __shared__ int sh[256];
    int t = threadIdx.x;
    int i0 = blockIdx.x * 1024 + t * 4;
    int v0 = (i0 + 0 < N) ? g_cnt[i0 + 0] : 0;
    int v1 = (i0 + 1 < N) ? g_cnt[i0 + 1] : 0;
    int v2 = (i0 + 2 < N) ? g_cnt[i0 + 2] : 0;
    int v3 = (i0 + 3 < N) ? g_cnt[i0 + 3] : 0;
    int s = v0 + v1 + v2 + v3;
    sh[t] = s;
    __syncthreads();
#pragma unroll
    for (int o = 1; o < 256; o <<= 1) {
        int a = 0;
        if (t >= o) a = sh[t - o];
        __syncthreads();
        sh[t] += a;
        __syncthreads();
    }
    int excl = sh[t] - s + g_bsum[blockIdx.x];
    if (i0 + 0 < N) g_off[i0 + 0] = excl;
    if (i0 + 1 < N) g_off[i0 + 1] = excl + v0;
    if (i0 + 2 < N) g_off[i0 + 2] = excl + v0 + v1;
    if (i0 + 3 < N) g_off[i0 + 3] = excl + v0 + v1 + v2;
}

// --------------------------------------------------- CSR edge scatter
__global__ void k_scatter(const int* __restrict__ ei, int E, int N) {
    int i = blockIdx.x * blockDim.x + threadIdx.x;
    if (i < E) {
        unsigned s = (unsigned)ei[i];
        unsigned d = (unsigned)ei[E + i];
        if (s < (unsigned)N && d < (unsigned)N) {
            int p = g_off[d] + atomicSub(&g_cnt[d], 1) - 1;
            g_esrc[p] = (int)s;
        }
    }
}

// ------------------------------------------ GEMM: hs = (x @ W) * dinv
// Register outer-product tiling: 256 thr, M=128 rows/block, 64 cols, K chunk 32.
// Thread (ty=tid>>4, tx=tid&15) owns rows ty*8..+7, cols tx*4..+3 (32 MACs/k).
// Per k: 2 LDS.128 (x, row-contiguous via transposed tile) + 1 LDS.128 (W)
// = 48B smem per 32 MACs (was 68B per 16).  f32x2 pairs rows; W broadcast-packed.
#define KC 32
#define XPAD 132   // 132*4 = 528 B row stride: 16B-aligned, odd-ish bank rotation
__global__ void __launch_bounds__(256) k_gemm(const float* __restrict__ x,
                                              const float* __restrict__ W, int N) {
    __shared__ __align__(16) float xsT[KC * XPAD];  // [k][row] transposed, 16.9KB
    __shared__ __align__(16) float Ws[KC * 64];     // [k][col], 8KB
    int tid = threadIdx.x;
    int row0 = blockIdx.x * 128;
    int tx = tid & 15;         // col group: c0 = tx*4
    int ty = tid >> 4;         // row group: r0 = ty*8
    int c0 = tx * 4;
    int r0 = ty * 8;

    const float4* x4 = (const float4*)x;
    const float4* W4 = (const float4*)W;

    // 16 f32x2 accumulators: [row-pair 0..3][col 0..3]
    unsigned long long acc[4][4];
#pragma unroll
    for (int i = 0; i < 4; i++)
#pragma unroll
        for (int j = 0; j < 4; j++) acc[i][j] = 0ull;

    for (int kc = 0; kc < 256 / KC; kc++) {
        // load W chunk [KC][64]: contiguous 2048 floats = 512 float4
#pragma unroll
        for (int i = tid; i < 512; i += 256) ((float4*)Ws)[i] = W4[kc * 512 + i];
        // load x chunk [128 rows][KC], store transposed xsT[k][row]
#pragma unroll
        for (int i = tid; i < 1024; i += 256) {
            int rr = i >> 3;           // row 0..127
            int cc = i & 7;            // float4 index within KC=32 floats
            float4 v = (row0 + rr < N) ? x4[(size_t)(row0 + rr) * 64 + kc * 8 + cc]
                                       : make_float4(0.f, 0.f, 0.f, 0.f);
            int kk = cc * 4;
            xsT[(kk + 0) * XPAD + rr] = v.x;
            xsT[(kk + 1) * XPAD + rr] = v.y;
            xsT[(kk + 2) * XPAD + rr] = v.z;
            xsT[(kk + 3) * XPAD + rr] = v.w;
        }
        __syncthreads();

#pragma unroll 4
        for (int k = 0; k < KC; k++) {
            // 8 x values (4 row-pairs), contiguous: 2x LDS.128
            const ulonglong2* xp = (const ulonglong2*)&xsT[k * XPAD + r0];
            ulonglong2 xA = xp[0];     // rows (r0,r0+1),(r0+2,r0+3)
            ulonglong2 xB = xp[1];     // rows (r0+4,r0+5),(r0+6,r0+7)
            // 4 W values: 1x LDS.128, broadcast-pack each
            float4 wv = *(const float4*)&Ws[k * 64 + c0];
            unsigned long long w0, w1, w2, w3;
            PACK2(w0, __float_as_uint(wv.x));
            PACK2(w1, __float_as_uint(wv.y));
            PACK2(w2, __float_as_uint(wv.z));
            PACK2(w3, __float_as_uint(wv.w));
            FMA2(acc[0][0], xA.x, w0); FMA2(acc[0][1], xA.x, w1);
            FMA2(acc[0][2], xA.x, w2); FMA2(acc[0][3], xA.x, w3);
            FMA2(acc[1][0], xA.y, w0); FMA2(acc[1][1], xA.y, w1);
            FMA2(acc[1][2], xA.y, w2); FMA2(acc[1][3], xA.y, w3);
            FMA2(acc[2][0], xB.x, w0); FMA2(acc[2][1], xB.x, w1);
            FMA2(acc[2][2], xB.x, w2); FMA2(acc[2][3], xB.x, w3);
            FMA2(acc[3][0], xB.y, w0); FMA2(acc[3][1], xB.y, w1);
            FMA2(acc[3][2], xB.y, w2); FMA2(acc[3][3], xB.y, w3);
        }
        __syncthreads();
    }

    // write back: row-pair rp covers rows r0+2rp, r0+2rp+1
#pragma unroll
    for (int rp = 0; rp < 4; rp++) {
        int rowA = row0 + r0 + 2 * rp;
        float2 c0v = *(float2*)&acc[rp][0];
        float2 c1v = *(float2*)&acc[rp][1];
        float2 c2v = *(float2*)&acc[rp][2];
        float2 c3v = *(float2*)&acc[rp][3];
        if (rowA < N) {
            float di = g_dinv[rowA];
            *(float4*)&g_hs[(size_t)rowA * HID + c0] =
                make_float4(c0v.x * di, c1v.x * di, c2v.x * di, c3v.x * di);
        }
        if (rowA + 1 < N) {
            float di = g_dinv[rowA + 1];
            *(float4*)&g_hs[(size_t)(rowA + 1) * HID + c0] =
                make_float4(c0v.y * di, c1v.y * di, c2v.y * di, c3v.y * di);
        }
    }
}

// -------------------------- SpMM gather + bias + dot(w2) + sigmoid
// one warp per node; half-warps own alternate edges; lane reads float4 (4 cols).
__global__ void k_spmm(const float* __restrict__ b, const float* __restrict__ w2,
                       const float* __restrict__ b2, float* __restrict__ out, int N) {
    int gwarp = (blockIdx.x * blockDim.x + threadIdx.x) >> 5;
    int lane  = threadIdx.x & 31;
    if (gwarp >= N) return;
    int n = gwarp;
    int half = lane >> 4;          // 0 or 1
    int cg   = lane & 15;          // float4 index within row

    int s = g_off[n];
    int e = g_off[n + 1];
    int cnt = e - s;
    const float4* hs4 = (const float4*)g_hs;

    float4 accA = make_float4(0.f, 0.f, 0.f, 0.f);
    float4 accB = make_float4(0.f, 0.f, 0.f, 0.f);
    int i = half;
    for (; i + 2 < cnt; i += 4) {
        int s0 = g_esrc[s + i];
        int s1 = g_esrc[s + i + 2];
        float4 v0 = hs4[(size_t)s0 * 16 + cg];
        float4 v1 = hs4[(size_t)s1 * 16 + cg];
        accA.x += v0.x; accA.y += v0.y; accA.z += v0.z; accA.w += v0.w;
        accB.x += v1.x; accB.y += v1.y; accB.z += v1.z; accB.w += v1.w;
    }
    if (i < cnt) {
        int s0 = g_esrc[s + i];
        float4 v0 = hs4[(size_t)s0 * 16 + cg];
        accA.x += v0.x; accA.y += v0.y; accA.z += v0.z; accA.w += v0.w;
    }
    accA.x += accB.x; accA.y += accB.y; accA.z += accB.z; accA.w += accB.w;
    accA.x += __shfl_xor_sync(0xFFFFFFFFu, accA.x, 16);
    accA.y += __shfl_xor_sync(0xFFFFFFFFu, accA.y, 16);
    accA.z += __shfl_xor_sync(0xFFFFFFFFu, accA.z, 16);
    accA.w += __shfl_xor_sync(0xFFFFFFFFu, accA.w, 16);

    float4 self = hs4[(size_t)n * 16 + cg];
    float di = g_dinv[n];
    float4 bb = ((const float4*)b)[cg];
    float4 ww = ((const float4*)w2)[cg];
    float p = (di * (accA.x + self.x) + bb.x) * ww.x
            + (di * (accA.y + self.y) + bb.y) * ww.y
            + (di * (accA.z + self.z) + bb.z) * ww.z
            + (di * (accA.w + self.w) + bb.w) * ww.w;
#pragma unroll
    for (int o = 8; o; o >>= 1) p += __shfl_xor_sync(0xFFFFFFFFu, p, o);
    if (lane == 0) {
        float z = p + b2[0];
        out[n] = 1.f / (1.f + expf(-z));
    }
}

// ---------------------------------------------------------------- launch
extern "C" void kernel_launch(void* const* d_in, const int* in_sizes, int n_in,
                              void* d_out, int out_size) {
    const float* x  = (const float*)d_in[0];
    const int*   ei = (const int*)d_in[1];    // int32 (JAX x64 disabled)
    const float* W  = (const float*)d_in[2];
    const float* b  = (const float*)d_in[3];
    const float* w2 = (const float*)d_in[4];
    const float* b2 = (const float*)d_in[5];
    float* out = (float*)d_out;

    int N = out_size;            // 100000 nodes
    int E = in_sizes[1] / 2;     // 1600000 edges
    int nb = (N + 1023) / 1024;  // scan blocks (<=128)

    k_init<<<(N + 255) / 256, 256>>>(N);
    k_count<<<(E + 255) / 256, 256>>>(ei + E, E, N);
    k_scan1<<<nb, 256>>>(N);
    k_gemm<<<(N + 127) / 128, 256>>>(x, W, N);   // slot 4 -> ncu profiles this
    k_scan2<<<1, 128>>>(nb, N);
    k_scan3<<<nb, 256>>>(N);
    k_scatter<<<(E + 255) / 256, 256>>>(ei, E, N);
    k_spmm<<<(N + 7) / 8, 256>>>(b, w2, b2, out, N);
}

// round 13
// speedup vs baseline: 2.7776x; 1.0253x over previous
#include <cuda_runtime.h>
#include <math.h>

#define HID 64
#define MAXN 100000
#define MAXE 1600000

// Scratch (allocation-free rule: __device__ globals). 16B-aligned for vector access.
__device__ __align__(16) int   g_cnt[MAXN];
__device__ __align__(16) int   g_off[MAXN + 1];
__device__ __align__(16) int   g_bsum[128];
__device__ __align__(16) int   g_esrc[MAXE];
__device__ __align__(16) float g_dinv[MAXN];
__device__ __align__(16) float g_hs[(size_t)MAXN * HID];

// dual-FMA: d = a*b + d on packed f32x2 (sm_100+). Accumulator tied through %0.
#define FMA2(d, a, b) asm("fma.rn.f32x2 %0, %1, %2, %0;" : "+l"(d) : "l"(a), "l"(b))
#define PACK2(out, v) asm("mov.b64 %0, {%1, %1};" : "=l"(out) : "r"(v))

// ---------------------------------------------------------------- init
__global__ void k_init(int N) {
    int i = blockIdx.x * blockDim.x + threadIdx.x;
    if (i < N) g_cnt[i] = 0;
}

// ------------------------------------------------------ degree histogram
__global__ void k_count(const int* __restrict__ dst, int E, int N) {
    int i = blockIdx.x * blockDim.x + threadIdx.x;
    if (i < E) {
        unsigned d = (unsigned)dst[i];
        if (d < (unsigned)N) atomicAdd(&g_cnt[d], 1);
    }
}

// ---------------- scan pass 1: per-block sums (1024 elems/block) + dinv
__global__ void k_scan1(int N) {
    int t = threadIdx.x;
    int i0 = blockIdx.x * 1024 + t * 4;
    int v0 = (i0 + 0 < N) ? g_cnt[i0 + 0] : 0;
    int v1 = (i0 + 1 < N) ? g_cnt[i0 + 1] : 0;
    int v2 = (i0 + 2 < N) ? g_cnt[i0 + 2] : 0;
    int v3 = (i0 + 3 < N) ? g_cnt[i0 + 3] : 0;
    if (i0 + 0 < N) g_dinv[i0 + 0] = rsqrtf((float)(v0 + 1));  // +1 self loop
    if (i0 + 1 < N) g_dinv[i0 + 1] = rsqrtf((float)(v1 + 1));
    if (i0 + 2 < N) g_dinv[i0 + 2] = rsqrtf((float)(v2 + 1));
    if (i0 + 3 < N) g_dinv[i0 + 3] = rsqrtf((float)(v3 + 1));
    int s = v0 + v1 + v2 + v3;
#pragma unroll
    for (int o = 16; o; o >>= 1) s += __shfl_xor_sync(0xFFFFFFFFu, s, o);
    __shared__ int wsum[8];
    if ((t & 31) == 0) wsum[t >> 5] = s;
    __syncthreads();
    if (t == 0) {
        int tot = 0;
#pragma unroll
        for (int w = 0; w < 8; w++) tot += wsum[w];
        g_bsum[blockIdx.x] = tot;
    }
}

// ---------------- scan pass 2: exclusive scan of <=128 block sums (1 block)
__global__ void k_scan2(int nb, int N) {
    __shared__ int sh[128];
    int t = threadIdx.x;
    int v = (t < nb) ? g_bsum[t] : 0;
    sh[t] = v;
    __syncthreads();
#pragma unroll
    for (int o = 1; o < 128; o <<= 1) {
        int a = 0;
        if (t >= o) a = sh[t - o];
        __syncthreads();
        sh[t] += a;
        __syncthreads();
    }
    if (t < nb) g_bsum[t] = sh[t] - v;     // exclusive
    if (t == 127) g_off[N] = sh[127];      // grand total
}

// ---------------- scan pass 3: local re-scan + block offset -> g_off
__global__ void k_scan3(int N) {
    __shared__ int sh[256];
    int t = threadIdx.x;
    int i0 = blockIdx.x * 1024 + t * 4;
    int v0 = (i0 + 0 < N) ? g_cnt[i0 + 0] : 0;
    int v1 = (i0 + 1 < N) ? g_cnt[i0 + 1] : 0;
    int v2 = (i0 + 2 < N) ? g_cnt[i0 + 2] : 0;
    int v3 = (i0 + 3 < N) ? g_cnt[i0 + 3] : 0;
    int s = v0 + v1 + v2 + v3;
    sh[t] = s;
    __syncthreads();
#pragma unroll
    for (int o = 1; o < 256; o <<= 1) {
        int a = 0;
        if (t >= o) a = sh[t - o];
        __syncthreads();
        sh[t] += a;
        __syncthreads();
    }
    int excl = sh[t] - s + g_bsum[blockIdx.x];
    if (i0 + 0 < N) g_off[i0 + 0] = excl;
    if (i0 + 1 < N) g_off[i0 + 1] = excl + v0;
    if (i0 + 2 < N) g_off[i0 + 2] = excl + v0 + v1;
    if (i0 + 3 < N) g_off[i0 + 3] = excl + v0 + v1 + v2;
}

// --------------------------------------------------- CSR edge scatter
__global__ void k_scatter(const int* __restrict__ ei, int E, int N) {
    int i = blockIdx.x * blockDim.x + threadIdx.x;
    if (i < E) {
        unsigned s = (unsigned)ei[i];
        unsigned d = (unsigned)ei[E + i];
        if (s < (unsigned)N && d < (unsigned)N) {
            int p = g_off[d] + atomicSub(&g_cnt[d], 1) - 1;
            g_esrc[p] = (int)s;
        }
    }
}

// ------------------------------------------ GEMM: hs = (x @ W) * dinv
// Register outer-product tiling + double-buffered software pipeline.
// 256 thr, M=128 rows/block, 64 cols, K chunk 32 (8 chunks).
// Thread (ty,tx) owns rows ty*8..+7, cols tx*4..+3 (32 MACs/k, 16 f32x2 acc).
// Per chunk: LDG chunk kc+1 -> regs, compute chunk kc from buf[cur],
// STS regs -> buf[1-cur], one __syncthreads per chunk (LDG latency hidden).
#define KC 32
#define XPAD 132   // 132*4 = 528 B row stride: 16B-aligned, odd-ish bank rotation
__global__ void __launch_bounds__(256) k_gemm(const float* __restrict__ x,
                                              const float* __restrict__ W, int N) {
    __shared__ __align__(16) float xsT[2][KC * XPAD];  // [buf][k][row] transposed
    __shared__ __align__(16) float Ws[2][KC * 64];     // [buf][k][col]
    int tid = threadIdx.x;
    int row0 = blockIdx.x * 128;
    int tx = tid & 15;
    int ty = tid >> 4;
    int c0 = tx * 4;
    int r0 = ty * 8;

    const float4* x4 = (const float4*)x;
    const float4* W4 = (const float4*)W;

    // staging registers for the next chunk
    float4 rw0, rw1;
    float4 rx[4];
    int rr_[4], cc_[4];
#pragma unroll
    for (int j = 0; j < 4; j++) { int idx = tid + j * 256; rr_[j] = idx >> 3; cc_[j] = idx & 7; }

    // 16 f32x2 accumulators: [row-pair][col]
    unsigned long long acc[4][4];
#pragma unroll
    for (int i = 0; i < 4; i++)
#pragma unroll
        for (int j = 0; j < 4; j++) acc[i][j] = 0ull;

    // ---- prologue: fetch chunk 0 and commit to buf 0
    {
        rw0 = W4[tid];
        rw1 = W4[256 + tid];
#pragma unroll
        for (int j = 0; j < 4; j++) {
            int rr = rr_[j];
            rx[j] = (row0 + rr < N) ? x4[(size_t)(row0 + rr) * 64 + cc_[j]]
                                    : make_float4(0.f, 0.f, 0.f, 0.f);
        }
        ((float4*)Ws[0])[tid] = rw0;
        ((float4*)Ws[0])[256 + tid] = rw1;
#pragma unroll
        for (int j = 0; j < 4; j++) {
            int rr = rr_[j], kk = cc_[j] * 4;
            xsT[0][(kk + 0) * XPAD + rr] = rx[j].x;
            xsT[0][(kk + 1) * XPAD + rr] = rx[j].y;
            xsT[0][(kk + 2) * XPAD + rr] = rx[j].z;
            xsT[0][(kk + 3) * XPAD + rr] = rx[j].w;
        }
    }
    __syncthreads();

    for (int kc = 0; kc < 8; kc++) {
        int cur = kc & 1;
        // ---- prefetch chunk kc+1 into registers (latency overlapped w/ compute)
        if (kc < 7) {
            rw0 = W4[(kc + 1) * 512 + tid];
            rw1 = W4[(kc + 1) * 512 + 256 + tid];
#pragma unroll
            for (int j = 0; j < 4; j++) {
                int rr = rr_[j];
                rx[j] = (row0 + rr < N)
                          ? x4[(size_t)(row0 + rr) * 64 + (kc + 1) * 8 + cc_[j]]
                          : make_float4(0.f, 0.f, 0.f, 0.f);
            }
        }

        // ---- compute on buf[cur]
        const float* xsc = xsT[cur];
        const float* wsc = Ws[cur];
#pragma unroll 4
        for (int k = 0; k < KC; k++) {
            const ulonglong2* xp = (const ulonglong2*)&xsc[k * XPAD + r0];
            ulonglong2 xA = xp[0];
            ulonglong2 xB = xp[1];
            float4 wv = *(const float4*)&wsc[k * 64 + c0];
            unsigned long long w0, w1, w2, w3;
            PACK2(w0, __float_as_uint(wv.x));
            PACK2(w1, __float_as_uint(wv.y));
            PACK2(w2, __float_as_uint(wv.z));
            PACK2(w3, __float_as_uint(wv.w));
            FMA2(acc[0][0], xA.x, w0); FMA2(acc[0][1], xA.x, w1);
            FMA2(acc[0][2], xA.x, w2); FMA2(acc[0][3], xA.x, w3);
            FMA2(acc[1][0], xA.y, w0); FMA2(acc[1][1], xA.y, w1);
            FMA2(acc[1][2], xA.y, w2); FMA2(acc[1][3], xA.y, w3);
            FMA2(acc[2][0], xB.x, w0); FMA2(acc[2][1], xB.x, w1);
            FMA2(acc[2][2], xB.x, w2); FMA2(acc[2][3], xB.x, w3);
            FMA2(acc[3][0], xB.y, w0); FMA2(acc[3][1], xB.y, w1);
            FMA2(acc[3][2], xB.y, w2); FMA2(acc[3][3], xB.y, w3);
        }

        // ---- commit prefetched chunk to the other buffer.
        // Safe: buf[1-cur] was last READ in iter kc-1; the sync ending iter kc-1
        // means every warp is past that read.
        if (kc < 7) {
            int nxt = 1 - cur;
            ((float4*)Ws[nxt])[tid] = rw0;
            ((float4*)Ws[nxt])[256 + tid] = rw1;
#pragma unroll
            for (int j = 0; j < 4; j++) {
                int rr = rr_[j], kk = cc_[j] * 4;
                xsT[nxt][(kk + 0) * XPAD + rr] = rx[j].x;
                xsT[nxt][(kk + 1) * XPAD + rr] = rx[j].y;
                xsT[nxt][(kk + 2) * XPAD + rr] = rx[j].z;
                xsT[nxt][(kk + 3) * XPAD + rr] = rx[j].w;
            }
        }
        __syncthreads();
    }

    // write back: row-pair rp covers rows r0+2rp, r0+2rp+1
#pragma unroll
    for (int rp = 0; rp < 4; rp++) {
        int rowA = row0 + r0 + 2 * rp;
        float2 c0v = *(float2*)&acc[rp][0];
        float2 c1v = *(float2*)&acc[rp][1];
        float2 c2v = *(float2*)&acc[rp][2];
        float2 c3v = *(float2*)&acc[rp][3];
        if (rowA < N) {
            float di = g_dinv[rowA];
            *(float4*)&g_hs[(size_t)rowA * HID + c0] =
                make_float4(c0v.x * di, c1v.x * di, c2v.x * di, c3v.x * di);
        }
        if (rowA + 1 < N) {
            float di = g_dinv[rowA + 1];
            *(float4*)&g_hs[(size_t)(rowA + 1) * HID + c0] =
                make_float4(c0v.y * di, c1v.y * di, c2v.y * di, c3v.y * di);
        }
    }
}

// -------------------------- SpMM gather + bias + dot(w2) + sigmoid
// one warp per node; half-warps own alternate edges; lane reads float4 (4 cols).
__global__ void k_spmm(const float* __restrict__ b, const float* __restrict__ w2,
                       const float* __restrict__ b2, float* __restrict__ out, int N) {
    int gwarp = (blockIdx.x * blockDim.x + threadIdx.x) >> 5;
    int lane  = threadIdx.x & 31;
    if (gwarp >= N) return;
    int n = gwarp;
    int half = lane >> 4;
    int cg   = lane & 15;

    int s = g_off[n];
    int e = g_off[n + 1];
    int cnt = e - s;
    const float4* hs4 = (const float4*)g_hs;

    float4 accA = make_float4(0.f, 0.f, 0.f, 0.f);
    float4 accB = make_float4(0.f, 0.f, 0.f, 0.f);
    int i = half;
    for (; i + 2 < cnt; i += 4) {
        int s0 = g_esrc[s + i];
        int s1 = g_esrc[s + i + 2];
        float4 v0 = hs4[(size_t)s0 * 16 + cg];
        float4 v1 = hs4[(size_t)s1 * 16 + cg];
        accA.x += v0.x; accA.y += v0.y; accA.z += v0.z; accA.w += v0.w;
        accB.x += v1.x; accB.y += v1.y; accB.z += v1.z; accB.w += v1.w;
    }
    if (i < cnt) {
        int s0 = g_esrc[s + i];
        float4 v0 = hs4[(size_t)s0 * 16 + cg];
        accA.x += v0.x; accA.y += v0.y; accA.z += v0.z; accA.w += v0.w;
    }
    accA.x += accB.x; accA.y += accB.y; accA.z += accB.z; accA.w += accB.w;
    accA.x += __shfl_xor_sync(0xFFFFFFFFu, accA.x, 16);
    accA.y += __shfl_xor_sync(0xFFFFFFFFu, accA.y, 16);
    accA.z += __shfl_xor_sync(0xFFFFFFFFu, accA.z, 16);
    accA.w += __shfl_xor_sync(0xFFFFFFFFu, accA.w, 16);

    float4 self = hs4[(size_t)n * 16 + cg];
    float di = g_dinv[n];
    float4 bb = ((const float4*)b)[cg];
    float4 ww = ((const float4*)w2)[cg];
    float p = (di * (accA.x + self.x) + bb.x) * ww.x
            + (di * (accA.y + self.y) + bb.y) * ww.y
            + (di * (accA.z + self.z) + bb.z) * ww.z
            + (di * (accA.w + self.w) + bb.w) * ww.w;
#pragma unroll
    for (int o = 8; o; o >>= 1) p += __shfl_xor_sync(0xFFFFFFFFu, p, o);
    if (lane == 0) {
        float z = p + b2[0];
        out[n] = 1.f / (1.f + expf(-z));
    }
}

// ---------------------------------------------------------------- launch
extern "C" void kernel_launch(void* const* d_in, const int* in_sizes, int n_in,
                              void* d_out, int out_size) {
    const float* x  = (const float*)d_in[0];
    const int*   ei = (const int*)d_in[1];    // int32 (JAX x64 disabled)
    const float* W  = (const float*)d_in[2];
    const float* b  = (const float*)d_in[3];
    const float* w2 = (const float*)d_in[4];
    const float* b2 = (const float*)d_in[5];
    float* out = (float*)d_out;

    int N = out_size;            // 100000 nodes
    int E = in_sizes[1] / 2;     // 1600000 edges
    int nb = (N + 1023) / 1024;  // scan blocks (<=128)

    k_init<<<(N + 255) / 256, 256>>>(N);
    k_count<<<(E + 255) / 256, 256>>>(ei + E, E, N);
    k_scan1<<<nb, 256>>>(N);
    k_gemm<<<(N + 127) / 128, 256>>>(x, W, N);   // slot 4 -> ncu profiles this
    k_scan2<<<1, 128>>>(nb, N);
    k_scan3<<<nb, 256>>>(N);
    k_scatter<<<(E + 255) / 256, 256>>>(ei, E, N);
    k_spmm<<<(N + 7) / 8, 256>>>(b, w2, b2, out, N);
}